// round 4
// baseline (speedup 1.0000x reference)
#include <cuda_runtime.h>
#include <cstdint>

// Problem constants
#define BTOK  65536
#define HID   512
#define DIN   512
#define NEXP  64
#define FOURE 256

// ---------------- scratch (static __device__, no allocation) ----------------
__device__ float g_q1[(size_t)BTOK * HID];   // qe1 output, reused for fused
__device__ float g_q [(size_t)BTOK * HID];   // qe2 output
__device__ float g_t [(size_t)BTOK * FOURE]; // tanh(fused @ Wg1^T)

// ---------------- Kahan-accurate tiled fp32 GEMM: C = act(A @ W^T) ----------
// FMA-Kahan compensated accumulation: result within ~2 ulp of the exact
// real-number dot product, eliminating accumulation-order divergence from the
// fp32 reference (whose own error is ~1e-6; ranking flips are driven by the
// DIFFERENCE between pipelines, which this minimizes).
// A is logically [M, K]; columns [0,K0) from A0 (row stride K0), columns
// [K0,K) from A1 (row stride K-K0).  W is [N, K] row-major. Biases are zero
// in this problem but kept for generality.
#define BM 128
#define BN 64
#define BKK 16

__global__ __launch_bounds__(256) void gemm_bias_act(
    const float* __restrict__ A0, const float* __restrict__ A1, int K0, int K,
    const float* __restrict__ W, const float* __restrict__ bias,
    float* __restrict__ C, int N, int act)
{
    __shared__ float As[BKK][BM];
    __shared__ float Bs[BKK][BN];

    const int tid  = threadIdx.x;
    const int m0   = blockIdx.y * BM;
    const int n0   = blockIdx.x * BN;
    const int lr   = tid >> 2;          // 0..63
    const int lc   = (tid & 3) << 2;    // 0,4,8,12 (float4 col)
    const int trow = (tid >> 4) << 3;   // 0..120 step 8
    const int tcol = (tid & 15) << 2;   // 0..60 step 4

    float s[8][4], c[8][4];
#pragma unroll
    for (int i = 0; i < 8; i++)
#pragma unroll
        for (int j = 0; j < 4; j++) { s[i][j] = 0.f; c[i][j] = 0.f; }

    for (int kt = 0; kt < K; kt += BKK) {
        const int gk = kt + lc;
        // A: rows lr and lr+64
        float4 av0, av1;
        if (gk < K0) {
            av0 = *(const float4*)(A0 + (size_t)(m0 + lr)      * K0 + gk);
            av1 = *(const float4*)(A0 + (size_t)(m0 + lr + 64) * K0 + gk);
        } else {
            const int K1 = K - K0;
            av0 = *(const float4*)(A1 + (size_t)(m0 + lr)      * K1 + (gk - K0));
            av1 = *(const float4*)(A1 + (size_t)(m0 + lr + 64) * K1 + (gk - K0));
        }
        // B: row lr (BN=64 rows exactly)
        const float4 bv = *(const float4*)(W + (size_t)(n0 + lr) * K + gk);

        As[lc + 0][lr] = av0.x; As[lc + 1][lr] = av0.y;
        As[lc + 2][lr] = av0.z; As[lc + 3][lr] = av0.w;
        As[lc + 0][lr + 64] = av1.x; As[lc + 1][lr + 64] = av1.y;
        As[lc + 2][lr + 64] = av1.z; As[lc + 3][lr + 64] = av1.w;

        Bs[lc + 0][lr] = bv.x; Bs[lc + 1][lr] = bv.y;
        Bs[lc + 2][lr] = bv.z; Bs[lc + 3][lr] = bv.w;

        __syncthreads();

#pragma unroll
        for (int k = 0; k < BKK; k++) {
            float a[8], b[4];
            *(float4*)&a[0] = *(const float4*)&As[k][trow];
            *(float4*)&a[4] = *(const float4*)&As[k][trow + 4];
            *(float4*)&b[0] = *(const float4*)&Bs[k][tcol];
#pragma unroll
            for (int i = 0; i < 8; i++)
#pragma unroll
                for (int j = 0; j < 4; j++) {
                    // FMA-Kahan step
                    float y = fmaf(a[i], b[j], -c[i][j]);
                    float t = s[i][j] + y;
                    c[i][j] = (t - s[i][j]) - y;
                    s[i][j] = t;
                }
        }
        __syncthreads();
    }

    float bb[4];
#pragma unroll
    for (int j = 0; j < 4; j++) bb[j] = bias ? bias[n0 + tcol + j] : 0.f;

#pragma unroll
    for (int i = 0; i < 8; i++) {
        float v[4];
#pragma unroll
        for (int j = 0; j < 4; j++) {
            float x = s[i][j] + bb[j];
            if (act == 1)       x = fmaxf(x, 0.f);
            else if (act == 2)  x = tanhf(x);
            v[j] = x;
        }
        float* cp = C + (size_t)(m0 + trow + i) * N + n0 + tcol;
        *(float4*)cp = *(float4*)&v[0];
    }
}

// ---------------- final: logits GEMM + softmax + top2 + scatter -------------
// One warp per token. Lane `l` owns experts l and l+32. Kahan accumulation
// for the logits (ranking-critical).
#define TPW 16          // tokens per warp
#define FIN_THREADS 256 // 8 warps -> 128 tokens per block

__global__ __launch_bounds__(FIN_THREADS) void final_kernel(
    const float* __restrict__ Wg2, float* __restrict__ out, int out_size)
{
    extern __shared__ float smem[];
    float* wg2s = smem;                 // [256*64]: wg2s[k*64 + e]
    float* trow = smem + FOURE * NEXP;  // [8][256]

    const int tid  = threadIdx.x;
    const int lane = tid & 31;
    const int warp = tid >> 5;

    for (int idx = tid; idx < NEXP * FOURE; idx += FIN_THREADS) {
        int e = idx >> 8;        // /256
        int k = idx & 255;
        wg2s[k * NEXP + e] = Wg2[idx];
    }
    __syncthreads();

    const int  OFF_L = BTOK * NEXP;
    const int  OFF_W = 2 * BTOK * NEXP;
    const int  OFF_I = 3 * BTOK * NEXP;
    const bool wl = out_size >= OFF_W;
    const bool ww = out_size >= OFF_I;
    const bool wi = out_size >= OFF_I + 2 * BTOK;

    float* ts = trow + warp * FOURE;
    const int token0 = blockIdx.x * (FIN_THREADS / 32 * TPW) + warp * TPW;

    for (int ti = 0; ti < TPW; ti++) {
        const int b = token0 + ti;

        const float4* src = (const float4*)(g_t + (size_t)b * FOURE);
        ((float4*)ts)[lane]      = src[lane];
        ((float4*)ts)[lane + 32] = src[lane + 32];
        __syncwarp();

        // logits for experts lane, lane+32 (FMA-Kahan)
        float l0 = 0.f, c0k = 0.f, l1 = 0.f, c1k = 0.f;
#pragma unroll 8
        for (int k = 0; k < FOURE; k++) {
            const float tv = ts[k];
            {
                float y = fmaf(tv, wg2s[k * NEXP + lane], -c0k);
                float t = l0 + y; c0k = (t - l0) - y; l0 = t;
            }
            {
                float y = fmaf(tv, wg2s[k * NEXP + lane + 32], -c1k);
                float t = l1 + y; c1k = (t - l1) - y; l1 = t;
            }
        }
        __syncwarp();

        // softmax over 64
        float m = fmaxf(l0, l1);
#pragma unroll
        for (int off = 16; off; off >>= 1)
            m = fmaxf(m, __shfl_xor_sync(0xffffffffu, m, off));
        const float e0 = expf(l0 - m);
        const float e1 = expf(l1 - m);
        float sden = e0 + e1;
#pragma unroll
        for (int off = 16; off; off >>= 1)
            sden += __shfl_xor_sync(0xffffffffu, sden, off);
        const float w0 = e0 / sden;
        const float w1 = e1 / sden;

        // top-1 (lower index wins ties -> matches jax.lax.top_k)
        float bv; int bi;
        if (w0 >= w1) { bv = w0; bi = lane; } else { bv = w1; bi = lane + 32; }
#pragma unroll
        for (int off = 16; off; off >>= 1) {
            float ov = __shfl_xor_sync(0xffffffffu, bv, off);
            int   oi = __shfl_xor_sync(0xffffffffu, bi, off);
            if (ov > bv || (ov == bv && oi < bi)) { bv = ov; bi = oi; }
        }
        // top-2 (exclude bi; weights >= 0 so -1 acts as -inf)
        float d0 = (lane == bi)      ? -1.f : w0;
        float d1 = (lane + 32 == bi) ? -1.f : w1;
        float bv2; int bi2;
        if (d0 >= d1) { bv2 = d0; bi2 = lane; } else { bv2 = d1; bi2 = lane + 32; }
#pragma unroll
        for (int off = 16; off; off >>= 1) {
            float ov = __shfl_xor_sync(0xffffffffu, bv2, off);
            int   oi = __shfl_xor_sync(0xffffffffu, bi2, off);
            if (ov > bv2 || (ov == bv2 && oi < bi2)) { bv2 = ov; bi2 = oi; }
        }

        const float denom = bv + bv2 + 1e-6f;
        const float r1 = bv / denom;
        const float r2 = bv2 / denom;

        const size_t base = (size_t)b * NEXP;
        const float cA = (lane == bi)      ? r1 : (lane == bi2)      ? r2 : 0.f;
        const float cB = (lane + 32 == bi) ? r1 : (lane + 32 == bi2) ? r2 : 0.f;
        out[base + lane]      = cA;
        out[base + lane + 32] = cB;
        if (wl) { out[OFF_L + base + lane] = l0; out[OFF_L + base + lane + 32] = l1; }
        if (ww) { out[OFF_W + base + lane] = w0; out[OFF_W + base + lane + 32] = w1; }
        if (wi && lane == 0) {
            out[OFF_I + (size_t)b * 2]     = (float)bi;
            out[OFF_I + (size_t)b * 2 + 1] = (float)bi2;
        }
        __syncwarp();
    }
}

// ---------------- launch ----------------------------------------------------
extern "C" void kernel_launch(void* const* d_in, const int* in_sizes, int n_in,
                              void* d_out, int out_size)
{
    const float* mm    = (const float*)d_in[0];
    const float* qf    = (const float*)d_in[1];
    const float* W_qe1 = (const float*)d_in[2];
    const float* b_qe1 = (const float*)d_in[3];
    const float* W_qe2 = (const float*)d_in[4];
    const float* b_qe2 = (const float*)d_in[5];
    const float* W_fus = (const float*)d_in[6];
    const float* b_fus = (const float*)d_in[7];
    const float* W_g1  = (const float*)d_in[8];
    const float* W_g2  = (const float*)d_in[9];
    float* out = (float*)d_out;

    float *p_q1, *p_q, *p_t;
    cudaGetSymbolAddress((void**)&p_q1, g_q1);
    cudaGetSymbolAddress((void**)&p_q,  g_q);
    cudaGetSymbolAddress((void**)&p_t,  g_t);

    const dim3 blk(256);
    const int mblocks = BTOK / BM;   // 512

    // q1 = relu(qf @ W_qe1^T + b_qe1)
    gemm_bias_act<<<dim3(HID / BN, mblocks), blk>>>(
        qf, nullptr, DIN, DIN, W_qe1, b_qe1, p_q1, HID, 1);
    // q = q1 @ W_qe2^T + b_qe2
    gemm_bias_act<<<dim3(HID / BN, mblocks), blk>>>(
        p_q1, nullptr, HID, HID, W_qe2, b_qe2, p_q, HID, 0);
    // fused = relu([mm | q] @ W_fus^T + b_fus)   (reuses g_q1)
    gemm_bias_act<<<dim3(HID / BN, mblocks), blk>>>(
        mm, p_q, HID, 2 * HID, W_fus, b_fus, p_q1, HID, 1);
    // t = tanh(fused @ W_g1^T)
    gemm_bias_act<<<dim3(FOURE / BN, mblocks), blk>>>(
        p_q1, nullptr, HID, HID, W_g1, nullptr, p_t, FOURE, 2);

    // logits + softmax + top2 + scatter + all outputs
    const int smem_bytes = (FOURE * NEXP + 8 * FOURE) * (int)sizeof(float); // 73728
    cudaFuncSetAttribute(final_kernel,
                         cudaFuncAttributeMaxDynamicSharedMemorySize, smem_bytes);
    final_kernel<<<BTOK / 128, FIN_THREADS, smem_bytes>>>(W_g2, out, out_size);
}

// round 5
// speedup vs baseline: 1.0354x; 1.0354x over previous
#include <cuda_runtime.h>
#include <cstdint>

// Problem constants
#define BTOK  65536
#define HID   512
#define DIN   512
#define NEXP  64
#define FOURE 256

// ---------------- scratch (static __device__, no allocation) ----------------
__device__ float g_q1[(size_t)BTOK * HID];   // qe1 output, reused for fused
__device__ float g_q [(size_t)BTOK * HID];   // qe2 output
__device__ float g_t [(size_t)BTOK * FOURE]; // tanh(fused @ Wg1^T)

// ---------------- packed f32x2 helpers (sm_103a) ----------------------------
typedef unsigned long long u64;

__device__ __forceinline__ u64 fma2(u64 a, u64 b, u64 c) {
    u64 d;
    asm("fma.rn.f32x2 %0, %1, %2, %3;" : "=l"(d) : "l"(a), "l"(b), "l"(c));
    return d;
}
__device__ __forceinline__ u64 add2(u64 a, u64 b) {
    u64 d;
    asm("add.rn.f32x2 %0, %1, %2;" : "=l"(d) : "l"(a), "l"(b));
    return d;
}
__device__ __forceinline__ u64 dup2(float x) {
    u64 d;
    asm("mov.b64 %0, {%1, %1};" : "=l"(d) : "f"(x));
    return d;
}
__device__ __forceinline__ float2 unpk2(u64 a) {
    float2 r;
    asm("mov.b64 {%0, %1}, %2;" : "=f"(r.x), "=f"(r.y) : "l"(a));
    return r;
}

// ---------------- Kahan-accurate tiled fp32 GEMM: C = act(A @ W^T) ----------
// Packed-f32x2 FMA-Kahan with NEGATED compensation (Cn == -c maintained
// exactly; bitwise identical per-lane to classic scalar FMA-Kahan):
//   y = fma2(a,b,Cn); t = add2(S,y); u = fma2(t,-1,S); Cn = add2(y,u); S = t
// Accumulators packed along adjacent output ROWS (a-pairs via LDS.64).
// A is logically [M, K]; columns [0,K0) from A0 (row stride K0), columns
// [K0,K) from A1 (row stride K-K0).  W is [N, K] row-major.
#define BM 128
#define BN 64
#define BKK 16

__global__ __launch_bounds__(256) void gemm_bias_act(
    const float* __restrict__ A0, const float* __restrict__ A1, int K0, int K,
    const float* __restrict__ W, const float* __restrict__ bias,
    float* __restrict__ C, int N, int act)
{
    __shared__ float As[BKK][BM];
    __shared__ float Bs[BKK][BN];

    const int tid  = threadIdx.x;
    const int m0   = blockIdx.y * BM;
    const int n0   = blockIdx.x * BN;
    const int lr   = tid >> 2;          // 0..63
    const int lc   = (tid & 3) << 2;    // 0,4,8,12 (float4 col)
    const int trow = (tid >> 4) << 3;   // 0..120 step 8
    const int tcol = (tid & 15) << 2;   // 0..60 step 4

    const u64 MONE = 0xbf800000bf800000ULL;  // (-1.0f, -1.0f)

    // S[pi][j]: rows (trow+2pi, trow+2pi+1), col tcol+j.  Cn = -compensation.
    u64 S[4][4], Cn[4][4];
#pragma unroll
    for (int pi = 0; pi < 4; pi++)
#pragma unroll
        for (int j = 0; j < 4; j++) { S[pi][j] = 0ull; Cn[pi][j] = 0ull; }

    for (int kt = 0; kt < K; kt += BKK) {
        const int gk = kt + lc;
        float4 av0, av1;
        if (gk < K0) {
            av0 = *(const float4*)(A0 + (size_t)(m0 + lr)      * K0 + gk);
            av1 = *(const float4*)(A0 + (size_t)(m0 + lr + 64) * K0 + gk);
        } else {
            const int K1 = K - K0;
            av0 = *(const float4*)(A1 + (size_t)(m0 + lr)      * K1 + (gk - K0));
            av1 = *(const float4*)(A1 + (size_t)(m0 + lr + 64) * K1 + (gk - K0));
        }
        const float4 bv = *(const float4*)(W + (size_t)(n0 + lr) * K + gk);

        As[lc + 0][lr] = av0.x; As[lc + 1][lr] = av0.y;
        As[lc + 2][lr] = av0.z; As[lc + 3][lr] = av0.w;
        As[lc + 0][lr + 64] = av1.x; As[lc + 1][lr + 64] = av1.y;
        As[lc + 2][lr + 64] = av1.z; As[lc + 3][lr + 64] = av1.w;

        Bs[lc + 0][lr] = bv.x; Bs[lc + 1][lr] = bv.y;
        Bs[lc + 2][lr] = bv.z; Bs[lc + 3][lr] = bv.w;

        __syncthreads();

#pragma unroll
        for (int k = 0; k < BKK; k++) {
            u64 ap[4];
#pragma unroll
            for (int pi = 0; pi < 4; pi++)
                ap[pi] = *(const u64*)&As[k][trow + 2 * pi];   // LDS.64 row pair
            u64 bd[4];
#pragma unroll
            for (int j = 0; j < 4; j++)
                bd[j] = dup2(Bs[k][tcol + j]);                 // (b, b)
#pragma unroll
            for (int j = 0; j < 4; j++)
#pragma unroll
                for (int pi = 0; pi < 4; pi++) {
                    u64 y = fma2(ap[pi], bd[j], Cn[pi][j]);
                    u64 t = add2(S[pi][j], y);
                    u64 u = fma2(t, MONE, S[pi][j]);   // s - t (exact -(t-s))
                    Cn[pi][j] = add2(y, u);            // y - (t - s)
                    S[pi][j]  = t;
                }
        }
        __syncthreads();
    }

    float bb[4];
#pragma unroll
    for (int j = 0; j < 4; j++) bb[j] = bias ? bias[n0 + tcol + j] : 0.f;

#pragma unroll
    for (int pi = 0; pi < 4; pi++) {
        float lo[4], hi[4];
#pragma unroll
        for (int j = 0; j < 4; j++) {
            float2 v = unpk2(S[pi][j]);
            float xl = v.x + bb[j];
            float xh = v.y + bb[j];
            if (act == 1)      { xl = fmaxf(xl, 0.f); xh = fmaxf(xh, 0.f); }
            else if (act == 2) { xl = tanhf(xl);      xh = tanhf(xh); }
            lo[j] = xl; hi[j] = xh;
        }
        float* cp0 = C + (size_t)(m0 + trow + 2 * pi)     * N + n0 + tcol;
        float* cp1 = C + (size_t)(m0 + trow + 2 * pi + 1) * N + n0 + tcol;
        *(float4*)cp0 = *(float4*)&lo[0];
        *(float4*)cp1 = *(float4*)&hi[0];
    }
}

// ---------------- final: logits GEMM + softmax + top2 + scatter -------------
// One warp per token. Lane `l` owns experts l and l+32. Kahan accumulation
// for the logits (ranking-critical) — unchanged from the passing round.
#define TPW 16          // tokens per warp
#define FIN_THREADS 256 // 8 warps -> 128 tokens per block

__global__ __launch_bounds__(FIN_THREADS) void final_kernel(
    const float* __restrict__ Wg2, float* __restrict__ out, int out_size)
{
    extern __shared__ float smem[];
    float* wg2s = smem;                 // [256*64]: wg2s[k*64 + e]
    float* trow = smem + FOURE * NEXP;  // [8][256]

    const int tid  = threadIdx.x;
    const int lane = tid & 31;
    const int warp = tid >> 5;

    for (int idx = tid; idx < NEXP * FOURE; idx += FIN_THREADS) {
        int e = idx >> 8;        // /256
        int k = idx & 255;
        wg2s[k * NEXP + e] = Wg2[idx];
    }
    __syncthreads();

    const int  OFF_L = BTOK * NEXP;
    const int  OFF_W = 2 * BTOK * NEXP;
    const int  OFF_I = 3 * BTOK * NEXP;
    const bool wl = out_size >= OFF_W;
    const bool ww = out_size >= OFF_I;
    const bool wi = out_size >= OFF_I + 2 * BTOK;

    float* ts = trow + warp * FOURE;
    const int token0 = blockIdx.x * (FIN_THREADS / 32 * TPW) + warp * TPW;

    for (int ti = 0; ti < TPW; ti++) {
        const int b = token0 + ti;

        const float4* src = (const float4*)(g_t + (size_t)b * FOURE);
        ((float4*)ts)[lane]      = src[lane];
        ((float4*)ts)[lane + 32] = src[lane + 32];
        __syncwarp();

        // logits for experts lane, lane+32 (FMA-Kahan)
        float l0 = 0.f, c0k = 0.f, l1 = 0.f, c1k = 0.f;
#pragma unroll 8
        for (int k = 0; k < FOURE; k++) {
            const float tv = ts[k];
            {
                float y = fmaf(tv, wg2s[k * NEXP + lane], -c0k);
                float t = l0 + y; c0k = (t - l0) - y; l0 = t;
            }
            {
                float y = fmaf(tv, wg2s[k * NEXP + lane + 32], -c1k);
                float t = l1 + y; c1k = (t - l1) - y; l1 = t;
            }
        }
        __syncwarp();

        // softmax over 64
        float m = fmaxf(l0, l1);
#pragma unroll
        for (int off = 16; off; off >>= 1)
            m = fmaxf(m, __shfl_xor_sync(0xffffffffu, m, off));
        const float e0 = expf(l0 - m);
        const float e1 = expf(l1 - m);
        float sden = e0 + e1;
#pragma unroll
        for (int off = 16; off; off >>= 1)
            sden += __shfl_xor_sync(0xffffffffu, sden, off);
        const float w0 = e0 / sden;
        const float w1 = e1 / sden;

        // top-1 (lower index wins ties -> matches jax.lax.top_k)
        float bv; int bi;
        if (w0 >= w1) { bv = w0; bi = lane; } else { bv = w1; bi = lane + 32; }
#pragma unroll
        for (int off = 16; off; off >>= 1) {
            float ov = __shfl_xor_sync(0xffffffffu, bv, off);
            int   oi = __shfl_xor_sync(0xffffffffu, bi, off);
            if (ov > bv || (ov == bv && oi < bi)) { bv = ov; bi = oi; }
        }
        // top-2 (exclude bi; weights >= 0 so -1 acts as -inf)
        float d0 = (lane == bi)      ? -1.f : w0;
        float d1 = (lane + 32 == bi) ? -1.f : w1;
        float bv2; int bi2;
        if (d0 >= d1) { bv2 = d0; bi2 = lane; } else { bv2 = d1; bi2 = lane + 32; }
#pragma unroll
        for (int off = 16; off; off >>= 1) {
            float ov = __shfl_xor_sync(0xffffffffu, bv2, off);
            int   oi = __shfl_xor_sync(0xffffffffu, bi2, off);
            if (ov > bv2 || (ov == bv2 && oi < bi2)) { bv2 = ov; bi2 = oi; }
        }

        const float denom = bv + bv2 + 1e-6f;
        const float r1 = bv / denom;
        const float r2 = bv2 / denom;

        const size_t base = (size_t)b * NEXP;
        const float cA = (lane == bi)      ? r1 : (lane == bi2)      ? r2 : 0.f;
        const float cB = (lane + 32 == bi) ? r1 : (lane + 32 == bi2) ? r2 : 0.f;
        out[base + lane]      = cA;
        out[base + lane + 32] = cB;
        if (wl) { out[OFF_L + base + lane] = l0; out[OFF_L + base + lane + 32] = l1; }
        if (ww) { out[OFF_W + base + lane] = w0; out[OFF_W + base + lane + 32] = w1; }
        if (wi && lane == 0) {
            out[OFF_I + (size_t)b * 2]     = (float)bi;
            out[OFF_I + (size_t)b * 2 + 1] = (float)bi2;
        }
        __syncwarp();
    }
}

// ---------------- launch ----------------------------------------------------
extern "C" void kernel_launch(void* const* d_in, const int* in_sizes, int n_in,
                              void* d_out, int out_size)
{
    const float* mm    = (const float*)d_in[0];
    const float* qf    = (const float*)d_in[1];
    const float* W_qe1 = (const float*)d_in[2];
    const float* b_qe1 = (const float*)d_in[3];
    const float* W_qe2 = (const float*)d_in[4];
    const float* b_qe2 = (const float*)d_in[5];
    const float* W_fus = (const float*)d_in[6];
    const float* b_fus = (const float*)d_in[7];
    const float* W_g1  = (const float*)d_in[8];
    const float* W_g2  = (const float*)d_in[9];
    float* out = (float*)d_out;

    float *p_q1, *p_q, *p_t;
    cudaGetSymbolAddress((void**)&p_q1, g_q1);
    cudaGetSymbolAddress((void**)&p_q,  g_q);
    cudaGetSymbolAddress((void**)&p_t,  g_t);

    const dim3 blk(256);
    const int mblocks = BTOK / BM;   // 512

    // q1 = relu(qf @ W_qe1^T + b_qe1)
    gemm_bias_act<<<dim3(HID / BN, mblocks), blk>>>(
        qf, nullptr, DIN, DIN, W_qe1, b_qe1, p_q1, HID, 1);
    // q = q1 @ W_qe2^T + b_qe2
    gemm_bias_act<<<dim3(HID / BN, mblocks), blk>>>(
        p_q1, nullptr, HID, HID, W_qe2, b_qe2, p_q, HID, 0);
    // fused = relu([mm | q] @ W_fus^T + b_fus)   (reuses g_q1)
    gemm_bias_act<<<dim3(HID / BN, mblocks), blk>>>(
        mm, p_q, HID, 2 * HID, W_fus, b_fus, p_q1, HID, 1);
    // t = tanh(fused @ W_g1^T)
    gemm_bias_act<<<dim3(FOURE / BN, mblocks), blk>>>(
        p_q1, nullptr, HID, HID, W_g1, nullptr, p_t, FOURE, 2);

    // logits + softmax + top2 + scatter + all outputs
    const int smem_bytes = (FOURE * NEXP + 8 * FOURE) * (int)sizeof(float); // 73728
    cudaFuncSetAttribute(final_kernel,
                         cudaFuncAttributeMaxDynamicSharedMemorySize, smem_bytes);
    final_kernel<<<BTOK / 128, FIN_THREADS, smem_bytes>>>(W_g2, out, out_size);
}

// round 6
// speedup vs baseline: 1.9156x; 1.8501x over previous
#include <cuda_runtime.h>
#include <cstdint>

// Problem constants
#define BTOK  65536
#define HID   512
#define DIN   512
#define NEXP  64
#define FOURE 256

// ---------------- scratch (static __device__, no allocation) ----------------
__device__ float g_q1[(size_t)BTOK * HID];   // qe1 output, reused for fused
__device__ float g_q [(size_t)BTOK * HID];   // qe2 output
__device__ float g_t [(size_t)BTOK * FOURE]; // tanh(fused @ Wg1^T)

// ---------------- packed f32x2 helpers (sm_103a) ----------------------------
typedef unsigned long long u64;

__device__ __forceinline__ u64 fma2(u64 a, u64 b, u64 c) {
    u64 d;
    asm("fma.rn.f32x2 %0, %1, %2, %3;" : "=l"(d) : "l"(a), "l"(b), "l"(c));
    return d;
}
__device__ __forceinline__ u64 add2(u64 a, u64 b) {
    u64 d;
    asm("add.rn.f32x2 %0, %1, %2;" : "=l"(d) : "l"(a), "l"(b));
    return d;
}
__device__ __forceinline__ u64 dup2(float x) {
    u64 d;
    asm("mov.b64 %0, {%1, %1};" : "=l"(d) : "f"(x));
    return d;
}
__device__ __forceinline__ float2 unpk2(u64 a) {
    float2 r;
    asm("mov.b64 {%0, %1}, %2;" : "=f"(r.x), "=f"(r.y) : "l"(a));
    return r;
}

// ---------------- chunked-Kahan tiled fp32 GEMM: C = act(A @ W^T) -----------
// Each BKK=16 k-tile accumulates with plain packed FMA into P (1 op / 2 MACs);
// P is then folded into (S, Cn) with a packed Kahan step (Cn = -compensation):
//   y = add2(P, Cn); t = add2(S, y); u = fma2(t,-1,S); Cn = add2(y,u); S = t
// Intra-chunk fp32 error ~2e-8/chunk; cross-chunk drift eliminated by Kahan.
// A is logically [M, K]; columns [0,K0) from A0 (row stride K0), columns
// [K0,K) from A1 (row stride K-K0).  W is [N, K] row-major.
#define BM 128
#define BN 64
#define BKK 16

__global__ __launch_bounds__(256, 2) void gemm_bias_act(
    const float* __restrict__ A0, const float* __restrict__ A1, int K0, int K,
    const float* __restrict__ W, const float* __restrict__ bias,
    float* __restrict__ C, int N, int act)
{
    __shared__ float As[BKK][BM];
    __shared__ float Bs[BKK][BN];

    const int tid  = threadIdx.x;
    const int m0   = blockIdx.y * BM;
    const int n0   = blockIdx.x * BN;
    const int lr   = tid >> 2;          // 0..63
    const int lc   = (tid & 3) << 2;    // 0,4,8,12 (float4 col)
    const int trow = (tid >> 4) << 3;   // 0..120 step 8
    const int tcol = (tid & 15) << 2;   // 0..60 step 4

    const u64 MONE = 0xbf800000bf800000ULL;  // (-1.0f, -1.0f)

    // S[pi][j]: rows (trow+2pi, trow+2pi+1), col tcol+j.  Cn = -compensation.
    u64 S[4][4], Cn[4][4];
#pragma unroll
    for (int pi = 0; pi < 4; pi++)
#pragma unroll
        for (int j = 0; j < 4; j++) { S[pi][j] = 0ull; Cn[pi][j] = 0ull; }

    for (int kt = 0; kt < K; kt += BKK) {
        const int gk = kt + lc;
        float4 av0, av1;
        if (gk < K0) {
            av0 = *(const float4*)(A0 + (size_t)(m0 + lr)      * K0 + gk);
            av1 = *(const float4*)(A0 + (size_t)(m0 + lr + 64) * K0 + gk);
        } else {
            const int K1 = K - K0;
            av0 = *(const float4*)(A1 + (size_t)(m0 + lr)      * K1 + (gk - K0));
            av1 = *(const float4*)(A1 + (size_t)(m0 + lr + 64) * K1 + (gk - K0));
        }
        const float4 bv = *(const float4*)(W + (size_t)(n0 + lr) * K + gk);

        As[lc + 0][lr] = av0.x; As[lc + 1][lr] = av0.y;
        As[lc + 2][lr] = av0.z; As[lc + 3][lr] = av0.w;
        As[lc + 0][lr + 64] = av1.x; As[lc + 1][lr + 64] = av1.y;
        As[lc + 2][lr + 64] = av1.z; As[lc + 3][lr + 64] = av1.w;

        Bs[lc + 0][lr] = bv.x; Bs[lc + 1][lr] = bv.y;
        Bs[lc + 2][lr] = bv.z; Bs[lc + 3][lr] = bv.w;

        __syncthreads();

        // chunk accumulators (plain packed FMA, 16 independent chains)
        u64 P[4][4];
#pragma unroll
        for (int pi = 0; pi < 4; pi++)
#pragma unroll
            for (int j = 0; j < 4; j++) P[pi][j] = 0ull;

#pragma unroll
        for (int k = 0; k < BKK; k++) {
            u64 ap[4];
#pragma unroll
            for (int pi = 0; pi < 4; pi++)
                ap[pi] = *(const u64*)&As[k][trow + 2 * pi];   // LDS.64 row pair
            u64 bd[4];
#pragma unroll
            for (int j = 0; j < 4; j++)
                bd[j] = dup2(Bs[k][tcol + j]);                 // (b, b)
#pragma unroll
            for (int j = 0; j < 4; j++)
#pragma unroll
                for (int pi = 0; pi < 4; pi++)
                    P[pi][j] = fma2(ap[pi], bd[j], P[pi][j]);
        }

        // Kahan fold of chunk sums into (S, Cn)
#pragma unroll
        for (int pi = 0; pi < 4; pi++)
#pragma unroll
            for (int j = 0; j < 4; j++) {
                u64 y = add2(P[pi][j], Cn[pi][j]);
                u64 t = add2(S[pi][j], y);
                u64 u = fma2(t, MONE, S[pi][j]);   // s - t (exact)
                Cn[pi][j] = add2(y, u);            // y - (t - s)
                S[pi][j]  = t;
            }

        __syncthreads();
    }

    float bb[4];
#pragma unroll
    for (int j = 0; j < 4; j++) bb[j] = bias ? bias[n0 + tcol + j] : 0.f;

#pragma unroll
    for (int pi = 0; pi < 4; pi++) {
        float lo[4], hi[4];
#pragma unroll
        for (int j = 0; j < 4; j++) {
            float2 v = unpk2(S[pi][j]);
            float xl = v.x + bb[j];
            float xh = v.y + bb[j];
            if (act == 1)      { xl = fmaxf(xl, 0.f); xh = fmaxf(xh, 0.f); }
            else if (act == 2) { xl = tanhf(xl);      xh = tanhf(xh); }
            lo[j] = xl; hi[j] = xh;
        }
        float* cp0 = C + (size_t)(m0 + trow + 2 * pi)     * N + n0 + tcol;
        float* cp1 = C + (size_t)(m0 + trow + 2 * pi + 1) * N + n0 + tcol;
        *(float4*)cp0 = *(float4*)&lo[0];
        *(float4*)cp1 = *(float4*)&hi[0];
    }
}

// ---------------- final: logits GEMM + softmax + top2 + scatter -------------
// One warp per token. Lane `l` owns experts l and l+32. Full Kahan for the
// logits (ranking-critical, cheap) — unchanged from the passing rounds.
#define TPW 16          // tokens per warp
#define FIN_THREADS 256 // 8 warps -> 128 tokens per block

__global__ __launch_bounds__(FIN_THREADS) void final_kernel(
    const float* __restrict__ Wg2, float* __restrict__ out, int out_size)
{
    extern __shared__ float smem[];
    float* wg2s = smem;                 // [256*64]: wg2s[k*64 + e]
    float* trow = smem + FOURE * NEXP;  // [8][256]

    const int tid  = threadIdx.x;
    const int lane = tid & 31;
    const int warp = tid >> 5;

    for (int idx = tid; idx < NEXP * FOURE; idx += FIN_THREADS) {
        int e = idx >> 8;        // /256
        int k = idx & 255;
        wg2s[k * NEXP + e] = Wg2[idx];
    }
    __syncthreads();

    const int  OFF_L = BTOK * NEXP;
    const int  OFF_W = 2 * BTOK * NEXP;
    const int  OFF_I = 3 * BTOK * NEXP;
    const bool wl = out_size >= OFF_W;
    const bool ww = out_size >= OFF_I;
    const bool wi = out_size >= OFF_I + 2 * BTOK;

    float* ts = trow + warp * FOURE;
    const int token0 = blockIdx.x * (FIN_THREADS / 32 * TPW) + warp * TPW;

    for (int ti = 0; ti < TPW; ti++) {
        const int b = token0 + ti;

        const float4* src = (const float4*)(g_t + (size_t)b * FOURE);
        ((float4*)ts)[lane]      = src[lane];
        ((float4*)ts)[lane + 32] = src[lane + 32];
        __syncwarp();

        // logits for experts lane, lane+32 (FMA-Kahan)
        float l0 = 0.f, c0k = 0.f, l1 = 0.f, c1k = 0.f;
#pragma unroll 8
        for (int k = 0; k < FOURE; k++) {
            const float tv = ts[k];
            {
                float y = fmaf(tv, wg2s[k * NEXP + lane], -c0k);
                float t = l0 + y; c0k = (t - l0) - y; l0 = t;
            }
            {
                float y = fmaf(tv, wg2s[k * NEXP + lane + 32], -c1k);
                float t = l1 + y; c1k = (t - l1) - y; l1 = t;
            }
        }
        __syncwarp();

        // softmax over 64
        float m = fmaxf(l0, l1);
#pragma unroll
        for (int off = 16; off; off >>= 1)
            m = fmaxf(m, __shfl_xor_sync(0xffffffffu, m, off));
        const float e0 = expf(l0 - m);
        const float e1 = expf(l1 - m);
        float sden = e0 + e1;
#pragma unroll
        for (int off = 16; off; off >>= 1)
            sden += __shfl_xor_sync(0xffffffffu, sden, off);
        const float w0 = e0 / sden;
        const float w1 = e1 / sden;

        // top-1 (lower index wins ties -> matches jax.lax.top_k)
        float bv; int bi;
        if (w0 >= w1) { bv = w0; bi = lane; } else { bv = w1; bi = lane + 32; }
#pragma unroll
        for (int off = 16; off; off >>= 1) {
            float ov = __shfl_xor_sync(0xffffffffu, bv, off);
            int   oi = __shfl_xor_sync(0xffffffffu, bi, off);
            if (ov > bv || (ov == bv && oi < bi)) { bv = ov; bi = oi; }
        }
        // top-2 (exclude bi; weights >= 0 so -1 acts as -inf)
        float d0 = (lane == bi)      ? -1.f : w0;
        float d1 = (lane + 32 == bi) ? -1.f : w1;
        float bv2; int bi2;
        if (d0 >= d1) { bv2 = d0; bi2 = lane; } else { bv2 = d1; bi2 = lane + 32; }
#pragma unroll
        for (int off = 16; off; off >>= 1) {
            float ov = __shfl_xor_sync(0xffffffffu, bv2, off);
            int   oi = __shfl_xor_sync(0xffffffffu, bi2, off);
            if (ov > bv2 || (ov == bv2 && oi < bi2)) { bv2 = ov; bi2 = oi; }
        }

        const float denom = bv + bv2 + 1e-6f;
        const float r1 = bv / denom;
        const float r2 = bv2 / denom;

        const size_t base = (size_t)b * NEXP;
        const float cA = (lane == bi)      ? r1 : (lane == bi2)      ? r2 : 0.f;
        const float cB = (lane + 32 == bi) ? r1 : (lane + 32 == bi2) ? r2 : 0.f;
        out[base + lane]      = cA;
        out[base + lane + 32] = cB;
        if (wl) { out[OFF_L + base + lane] = l0; out[OFF_L + base + lane + 32] = l1; }
        if (ww) { out[OFF_W + base + lane] = w0; out[OFF_W + base + lane + 32] = w1; }
        if (wi && lane == 0) {
            out[OFF_I + (size_t)b * 2]     = (float)bi;
            out[OFF_I + (size_t)b * 2 + 1] = (float)bi2;
        }
        __syncwarp();
    }
}

// ---------------- launch ----------------------------------------------------
extern "C" void kernel_launch(void* const* d_in, const int* in_sizes, int n_in,
                              void* d_out, int out_size)
{
    const float* mm    = (const float*)d_in[0];
    const float* qf    = (const float*)d_in[1];
    const float* W_qe1 = (const float*)d_in[2];
    const float* b_qe1 = (const float*)d_in[3];
    const float* W_qe2 = (const float*)d_in[4];
    const float* b_qe2 = (const float*)d_in[5];
    const float* W_fus = (const float*)d_in[6];
    const float* b_fus = (const float*)d_in[7];
    const float* W_g1  = (const float*)d_in[8];
    const float* W_g2  = (const float*)d_in[9];
    float* out = (float*)d_out;

    float *p_q1, *p_q, *p_t;
    cudaGetSymbolAddress((void**)&p_q1, g_q1);
    cudaGetSymbolAddress((void**)&p_q,  g_q);
    cudaGetSymbolAddress((void**)&p_t,  g_t);

    const dim3 blk(256);
    const int mblocks = BTOK / BM;   // 512

    // q1 = relu(qf @ W_qe1^T + b_qe1)
    gemm_bias_act<<<dim3(HID / BN, mblocks), blk>>>(
        qf, nullptr, DIN, DIN, W_qe1, b_qe1, p_q1, HID, 1);
    // q = q1 @ W_qe2^T + b_qe2
    gemm_bias_act<<<dim3(HID / BN, mblocks), blk>>>(
        p_q1, nullptr, HID, HID, W_qe2, b_qe2, p_q, HID, 0);
    // fused = relu([mm | q] @ W_fus^T + b_fus)   (reuses g_q1)
    gemm_bias_act<<<dim3(HID / BN, mblocks), blk>>>(
        mm, p_q, HID, 2 * HID, W_fus, b_fus, p_q1, HID, 1);
    // t = tanh(fused @ W_g1^T)
    gemm_bias_act<<<dim3(FOURE / BN, mblocks), blk>>>(
        p_q1, nullptr, HID, HID, W_g1, nullptr, p_t, FOURE, 2);

    // logits + softmax + top2 + scatter + all outputs
    const int smem_bytes = (FOURE * NEXP + 8 * FOURE) * (int)sizeof(float); // 73728
    cudaFuncSetAttribute(final_kernel,
                         cudaFuncAttributeMaxDynamicSharedMemorySize, smem_bytes);
    final_kernel<<<BTOK / 128, FIN_THREADS, smem_bytes>>>(W_g2, out, out_size);
}